// round 2
// baseline (speedup 1.0000x reference)
#include <cuda_runtime.h>
#include <math.h>

#define Dm 1024
#define Ne 12
#define Nt 2048
#define HSdim 2048
#define HRdim 3072
#define TAUf 1.5f

// -------- scratch (static device arrays; no allocation) --------
__device__ float g_Hs[(long)Nt * 2 * HSdim];       // 2048 x 4096
__device__ float g_Aact[(long)Nt * HSdim];         // 2048 x 2048
__device__ float g_ys[(long)Nt * Dm];              // 2048 x 1024
__device__ float g_Hr[(long)2 * Nt * 2 * HRdim];   // 4096 x 6144
__device__ float g_Ar[(long)2 * Nt * HRdim];       // 4096 x 3072
__device__ float g_yE[(long)2 * Nt * Dm];          // 4096 x 1024
__device__ int   g_top[Nt * 2];
__device__ float g_w[Nt * 2];
__device__ int   g_cnt[Ne];
__device__ int   g_offs[Ne + 1];
__device__ int   g_rank[Nt * 2];
__device__ int   g_tokrow[2 * Nt];
__device__ int   g_slot[Nt * 2];

// -------- router: logits, top-2, softmax weights --------
__global__ void router_kernel(const float* __restrict__ x,
                              const float* __restrict__ Wr,
                              const float* __restrict__ br) {
    int n = blockIdx.x;
    __shared__ float sx[Dm];
    __shared__ float slog[Ne];
    for (int k = threadIdx.x; k < Dm; k += blockDim.x) sx[k] = x[(long)n * Dm + k];
    __syncthreads();
    int e = threadIdx.x;
    if (e < Ne) {
        float s = 0.f;
        #pragma unroll 8
        for (int k = 0; k < Dm; k++) s += sx[k] * Wr[k * Ne + e];
        slog[e] = (s + br[e]) / TAUf;
    }
    __syncthreads();
    if (threadIdx.x == 0) {
        int i0 = 0; float v0 = slog[0];
        for (int j = 1; j < Ne; j++) if (slog[j] > v0) { v0 = slog[j]; i0 = j; }
        int i1 = -1; float v1 = -1e30f;
        for (int j = 0; j < Ne; j++) if (j != i0 && slog[j] > v1) { v1 = slog[j]; i1 = j; }
        float e1 = expf(v1 - v0);
        float z = 1.0f + e1;
        g_top[n * 2 + 0] = i0; g_top[n * 2 + 1] = i1;
        g_w[n * 2 + 0] = 1.0f / z; g_w[n * 2 + 1] = e1 / z;
    }
}

__global__ void zero_cnt_kernel() { if (threadIdx.x < Ne) g_cnt[threadIdx.x] = 0; }

__global__ void count_kernel() {
    int i = blockIdx.x * blockDim.x + threadIdx.x;
    if (i < 2 * Nt) g_rank[i] = atomicAdd(&g_cnt[g_top[i]], 1);
}

__global__ void offs_kernel() {
    int o = 0;
    for (int e = 0; e < Ne; e++) { g_offs[e] = o; o += g_cnt[e]; }
    g_offs[Ne] = o;
}

__global__ void fill_kernel() {
    int i = blockIdx.x * blockDim.x + threadIdx.x;
    if (i < 2 * Nt) {
        int e = g_top[i];
        int r = g_offs[e] + g_rank[i];
        g_tokrow[r] = i >> 1;
        g_slot[i] = r;
    }
}

// -------- generic SGEMM: C[(rowbase+r)*N + c] = sum_k A[row(r)][k]*B[k][c] + bias[c]
// Optional expert batching via blockIdx.z (cnt/offs/strides), optional row gather.
__global__ void __launch_bounds__(256)
sgemm128(const float* __restrict__ A,
         const float* __restrict__ Bb,
         const float* __restrict__ biasb,
         float* __restrict__ C,
         int Mfixed, int N, int K,
         const int* __restrict__ cnt,
         const int* __restrict__ offs,
         const int* __restrict__ rowidx,
         long strideB, int strideBias) {
    int e = blockIdx.z;
    int M, rowbase;
    if (cnt) { M = cnt[e]; rowbase = offs[e]; }
    else     { M = Mfixed; rowbase = 0; }
    int bm = blockIdx.y * 128;
    if (bm >= M) return;
    int bn = blockIdx.x * 128;
    const float* B = Bb + (long)e * strideB;
    const float* bias = biasb + (long)e * strideBias;

    __shared__ float As[8][128];
    __shared__ float Bs[8][128];

    int tid = threadIdx.x;
    int arow = tid >> 1;
    int acol = (tid & 1) << 2;
    int brow = tid >> 5;
    int bcol = (tid & 31) << 2;
    int tx = tid & 15;
    int ty = tid >> 4;

    int gar = bm + arow;
    bool aok = gar < M;
    long arowg = 0;
    if (aok) arowg = rowidx ? (long)rowidx[rowbase + gar] : (long)(rowbase + gar);
    const float* Arow = A + arowg * (long)K;

    float acc[8][8];
    #pragma unroll
    for (int i = 0; i < 8; i++)
        #pragma unroll
        for (int j = 0; j < 8; j++) acc[i][j] = 0.f;

    for (int k0 = 0; k0 < K; k0 += 8) {
        float4 av = aok ? *(const float4*)(Arow + k0 + acol)
                        : make_float4(0.f, 0.f, 0.f, 0.f);
        As[acol + 0][arow] = av.x;
        As[acol + 1][arow] = av.y;
        As[acol + 2][arow] = av.z;
        As[acol + 3][arow] = av.w;
        *(float4*)&Bs[brow][bcol] =
            *(const float4*)(B + (long)(k0 + brow) * N + bn + bcol);
        __syncthreads();
        #pragma unroll
        for (int k = 0; k < 8; k++) {
            float4 a0 = *(const float4*)&As[k][ty * 8];
            float4 a1 = *(const float4*)&As[k][ty * 8 + 4];
            float4 b0 = *(const float4*)&Bs[k][tx * 8];
            float4 b1 = *(const float4*)&Bs[k][tx * 8 + 4];
            float af[8] = {a0.x, a0.y, a0.z, a0.w, a1.x, a1.y, a1.z, a1.w};
            float bf[8] = {b0.x, b0.y, b0.z, b0.w, b1.x, b1.y, b1.z, b1.w};
            #pragma unroll
            for (int i = 0; i < 8; i++)
                #pragma unroll
                for (int j = 0; j < 8; j++)
                    acc[i][j] += af[i] * bf[j];
        }
        __syncthreads();
    }

    #pragma unroll
    for (int i = 0; i < 8; i++) {
        int r = bm + ty * 8 + i;
        if (r < M) {
            float* Crow = C + (long)(rowbase + r) * N + bn + tx * 8;
            const float* bp = bias + bn + tx * 8;
            #pragma unroll
            for (int j = 0; j < 8; j++) Crow[j] = acc[i][j] + bp[j];
        }
    }
}

// -------- GEGLU: O[m][j] = H[m][j] * gelu_exact(H[m][W+j]), H width 2W --------
__global__ void geglu_kernel(const float* __restrict__ H, float* __restrict__ O,
                             int rows, int W) {
    long idx = (long)blockIdx.x * blockDim.x + threadIdx.x;
    long total = (long)rows * W;
    if (idx >= total) return;
    long m = idx / W;
    int j = (int)(idx - m * W);
    float a = H[m * 2 * W + j];
    float g = H[m * 2 * W + W + j];
    float gel = 0.5f * g * (1.0f + erff(g * 0.70710678118654752f));
    O[idx] = a * gel;
}

// -------- combine: out = ys + w0*yE[slot0] + w1*yE[slot1] --------
__global__ void combine_kernel(const float* __restrict__ ys,
                               const float* __restrict__ yE,
                               float* __restrict__ out) {
    int idx = blockIdx.x * blockDim.x + threadIdx.x;  // < Nt*Dm
    int n = idx >> 10;
    int d = idx & (Dm - 1);
    float v = ys[idx];
    int s0 = g_slot[n * 2 + 0], s1 = g_slot[n * 2 + 1];
    float w0 = g_w[n * 2 + 0], w1 = g_w[n * 2 + 1];
    v += w0 * yE[(long)s0 * Dm + d] + w1 * yE[(long)s1 * Dm + d];
    out[idx] = v;
}

extern "C" void kernel_launch(void* const* d_in, const int* in_sizes, int n_in,
                              void* d_out, int out_size) {
    const float* x   = (const float*)d_in[0];
    const float* Ws1 = (const float*)d_in[1];
    const float* bs1 = (const float*)d_in[2];
    const float* Ws2 = (const float*)d_in[3];
    const float* bs2 = (const float*)d_in[4];
    const float* We1 = (const float*)d_in[5];
    const float* be1 = (const float*)d_in[6];
    const float* We2 = (const float*)d_in[7];
    const float* be2 = (const float*)d_in[8];
    const float* Wr  = (const float*)d_in[9];
    const float* br  = (const float*)d_in[10];
    float* out = (float*)d_out;

    float *pHs, *pAact, *pys, *pHr, *pAr, *pyE;
    int *pcnt, *poffs, *ptok;
    cudaGetSymbolAddress((void**)&pHs,   g_Hs);
    cudaGetSymbolAddress((void**)&pAact, g_Aact);
    cudaGetSymbolAddress((void**)&pys,   g_ys);
    cudaGetSymbolAddress((void**)&pHr,   g_Hr);
    cudaGetSymbolAddress((void**)&pAr,   g_Ar);
    cudaGetSymbolAddress((void**)&pyE,   g_yE);
    cudaGetSymbolAddress((void**)&pcnt,  g_cnt);
    cudaGetSymbolAddress((void**)&poffs, g_offs);
    cudaGetSymbolAddress((void**)&ptok,  g_tokrow);

    // 1) routing
    router_kernel<<<Nt, 128>>>(x, Wr, br);
    zero_cnt_kernel<<<1, 32>>>();
    count_kernel<<<(2 * Nt + 255) / 256, 256>>>();
    offs_kernel<<<1, 1>>>();
    fill_kernel<<<(2 * Nt + 255) / 256, 256>>>();

    // 2) shared expert
    sgemm128<<<dim3(2 * HSdim / 128, Nt / 128, 1), 256>>>(
        x, Ws1, bs1, pHs, Nt, 2 * HSdim, Dm,
        nullptr, nullptr, nullptr, 0, 0);
    {
        long tot = (long)Nt * HSdim;
        geglu_kernel<<<(unsigned)((tot + 255) / 256), 256>>>(pHs, pAact, Nt, HSdim);
    }
    sgemm128<<<dim3(Dm / 128, Nt / 128, 1), 256>>>(
        pAact, Ws2, bs2, pys, Nt, Dm, HSdim,
        nullptr, nullptr, nullptr, 0, 0);

    // 3) routed experts (sparse dispatch: 4096 gathered rows total)
    sgemm128<<<dim3(2 * HRdim / 128, Nt / 128, Ne), 256>>>(
        x, We1, be1, pHr, 0, 2 * HRdim, Dm,
        pcnt, poffs, ptok, (long)Dm * 2 * HRdim, 2 * HRdim);
    {
        long tot = (long)2 * Nt * HRdim;
        geglu_kernel<<<(unsigned)((tot + 255) / 256), 256>>>(pHr, pAr, 2 * Nt, HRdim);
    }
    sgemm128<<<dim3(Dm / 128, Nt / 128, Ne), 256>>>(
        pAr, We2, be2, pyE, 0, Dm, HRdim,
        pcnt, poffs, nullptr, (long)HRdim * Dm, Dm);

    // 4) combine
    combine_kernel<<<(Nt * Dm) / 256, 256>>>(pys, pyE, out);
}

// round 9
// speedup vs baseline: 2.4515x; 2.4515x over previous
#include <cuda_runtime.h>
#include <math.h>
#include <cstdint>

#define Dm 1024
#define Ne 12
#define Nt 2048
#define HSdim 2048
#define HRdim 3072
#define TAUf 1.5f

// ---------------- scratch (static device arrays; no allocation) ----------------
__device__ float g_Hs[(long)Nt * 2 * HSdim];       // 2048 x 4096
__device__ float g_Aact[(long)Nt * HSdim];         // 2048 x 2048
__device__ float g_ys[(long)Nt * Dm];              // 2048 x 1024
__device__ float g_Hr[(long)2 * Nt * 2 * HRdim];   // 4096 x 6144
__device__ float g_Ar[(long)2 * Nt * HRdim];       // 4096 x 3072
__device__ float g_yE[(long)2 * Nt * Dm];          // 4096 x 1024
__device__ int   g_top[Nt * 2];
__device__ float g_w[Nt * 2];
__device__ int   g_cnt[Ne];
__device__ int   g_offs[Ne + 1];
__device__ int   g_rank[Nt * 2];
__device__ int   g_tokrow[2 * Nt];
__device__ int   g_slot[Nt * 2];

// ---------------- helpers ----------------
__device__ __forceinline__ uint32_t f2tf32(float x) {
    uint32_t r;
    asm("cvt.rna.tf32.f32 %0, %1;" : "=r"(r) : "f"(x));
    return r;
}
__device__ __forceinline__ void mma_tf32(float* d, const uint32_t* a, const uint32_t* b) {
    asm volatile(
        "mma.sync.aligned.m16n8k8.row.col.f32.tf32.tf32.f32 "
        "{%0,%1,%2,%3}, {%4,%5,%6,%7}, {%8,%9}, {%0,%1,%2,%3};"
        : "+f"(d[0]), "+f"(d[1]), "+f"(d[2]), "+f"(d[3])
        : "r"(a[0]), "r"(a[1]), "r"(a[2]), "r"(a[3]), "r"(b[0]), "r"(b[1]));
}

// ---------------- routing kernels ----------------
__global__ void router_kernel(const float* __restrict__ x,
                              const float* __restrict__ Wr,
                              const float* __restrict__ br) {
    int n = blockIdx.x;
    __shared__ float sx[Dm];
    __shared__ float slog[Ne];
    for (int k = threadIdx.x; k < Dm; k += blockDim.x) sx[k] = x[(long)n * Dm + k];
    __syncthreads();
    int e = threadIdx.x;
    if (e < Ne) {
        float s = 0.f;
        #pragma unroll 8
        for (int k = 0; k < Dm; k++) s += sx[k] * Wr[k * Ne + e];
        slog[e] = (s + br[e]) / TAUf;
    }
    __syncthreads();
    if (threadIdx.x == 0) {
        int i0 = 0; float v0 = slog[0];
        for (int j = 1; j < Ne; j++) if (slog[j] > v0) { v0 = slog[j]; i0 = j; }
        int i1 = -1; float v1 = -1e30f;
        for (int j = 0; j < Ne; j++) if (j != i0 && slog[j] > v1) { v1 = slog[j]; i1 = j; }
        float e1 = expf(v1 - v0);
        float z = 1.0f + e1;
        g_top[n * 2 + 0] = i0; g_top[n * 2 + 1] = i1;
        g_w[n * 2 + 0] = 1.0f / z; g_w[n * 2 + 1] = e1 / z;
    }
}
__global__ void zero_cnt_kernel() { if (threadIdx.x < Ne) g_cnt[threadIdx.x] = 0; }
__global__ void count_kernel() {
    int i = blockIdx.x * blockDim.x + threadIdx.x;
    if (i < 2 * Nt) g_rank[i] = atomicAdd(&g_cnt[g_top[i]], 1);
}
__global__ void offs_kernel() {
    int o = 0;
    for (int e = 0; e < Ne; e++) { g_offs[e] = o; o += g_cnt[e]; }
    g_offs[Ne] = o;
}
__global__ void fill_kernel() {
    int i = blockIdx.x * blockDim.x + threadIdx.x;
    if (i < 2 * Nt) {
        int e = g_top[i];
        int r = g_offs[e] + g_rank[i];
        g_tokrow[r] = i >> 1;
        g_slot[i] = r;
    }
}

// ---------------- TF32 mma.sync GEMM ----------------
// C[(rowbase+r)][n] = sum_k A[row(r)][k] * B[k][n] + bias[n]
// Tile 128x128x32, 256 threads, warps 2(M) x 4(N), warp tile 64x32.
#define BM 128
#define BN 128
#define BK 32
#define SSTR 136   // smem row stride in words: bank(frag) = 8c+g, conflict-free

__global__ void __launch_bounds__(256, 2)
tf32gemm(const float* __restrict__ A,
         const float* __restrict__ Bb,
         const float* __restrict__ biasb,
         float* __restrict__ C,
         int Mfixed, int N, int K,
         const int* __restrict__ cnt,
         const int* __restrict__ offs,
         const int* __restrict__ rowidx,
         long strideB, int strideBias) {
    __shared__ float As[BK][SSTR];
    __shared__ float Bs[BK][SSTR];

    int tid = threadIdx.x;
    int w = tid >> 5, l = tid & 31;
    int g = l >> 2, c = l & 3;
    int wm = w >> 2, wn = w & 3;       // warp grid 2 x 4

    int e = blockIdx.z;
    int M, rowbase;
    if (cnt) { M = cnt[e]; rowbase = offs[e]; }
    else     { M = Mfixed; rowbase = 0; }
    const float* B = Bb + (long)e * strideB;
    const float* bias = biasb + (long)e * strideBias;
    int bn = blockIdx.x * BN;

    int am = tid & 127;                // A tile row this thread loads
    int akoff = (tid >> 7) * 16;       // k offset (0 or 16)

    for (int bm = blockIdx.y * BM; bm < M; bm += gridDim.y * BM) {
        // resolve this thread's A source row
        int r = bm + am;
        if (r >= M) r = bm;            // clamp to valid (results unused)
        long ga = rowidx ? (long)rowidx[rowbase + r] : (long)(rowbase + r);
        const float* Arow = A + ga * (long)K;

        float acc[4][4][4];
        #pragma unroll
        for (int mt = 0; mt < 4; mt++)
            #pragma unroll
            for (int nt = 0; nt < 4; nt++)
                #pragma unroll
                for (int i = 0; i < 4; i++) acc[mt][nt][i] = 0.f;

        for (int k0 = 0; k0 < K; k0 += BK) {
            // --- A tile: 128 rows x 32 k (cvt to tf32 at store) ---
            #pragma unroll
            for (int i = 0; i < 4; i++) {
                float4 v = *(const float4*)(Arow + k0 + akoff + i * 4);
                int kk = akoff + i * 4;
                As[kk + 0][am] = __uint_as_float(f2tf32(v.x));
                As[kk + 1][am] = __uint_as_float(f2tf32(v.y));
                As[kk + 2][am] = __uint_as_float(f2tf32(v.z));
                As[kk + 3][am] = __uint_as_float(f2tf32(v.w));
            }
            // --- B tile: 32 k-rows x 128 n ---
            #pragma unroll
            for (int i = 0; i < 4; i++) {
                int idx = tid + i * 256;
                int kk = idx >> 5, n4 = (idx & 31) << 2;
                float4 v = *(const float4*)(B + (long)(k0 + kk) * N + bn + n4);
                float4 o;
                o.x = __uint_as_float(f2tf32(v.x));
                o.y = __uint_as_float(f2tf32(v.y));
                o.z = __uint_as_float(f2tf32(v.z));
                o.w = __uint_as_float(f2tf32(v.w));
                *(float4*)&Bs[kk][n4] = o;
            }
            __syncthreads();

            #pragma unroll
            for (int ks = 0; ks < 4; ks++) {
                int kk = ks * 8;
                uint32_t af[4][4], bf[4][2];
                #pragma unroll
                for (int mt = 0; mt < 4; mt++) {
                    int rm = wm * 64 + mt * 16;
                    af[mt][0] = __float_as_uint(As[kk + c][rm + g]);
                    af[mt][1] = __float_as_uint(As[kk + c][rm + g + 8]);
                    af[mt][2] = __float_as_uint(As[kk + c + 4][rm + g]);
                    af[mt][3] = __float_as_uint(As[kk + c + 4][rm + g + 8]);
                }
                #pragma unroll
                for (int nt = 0; nt < 4; nt++) {
                    int cn = wn * 32 + nt * 8;
                    bf[nt][0] = __float_as_uint(Bs[kk + c][cn + g]);
                    bf[nt][1] = __float_as_uint(Bs[kk + c + 4][cn + g]);
                }
                #pragma unroll
                for (int mt = 0; mt < 4; mt++)
                    #pragma unroll
                    for (int nt = 0; nt < 4; nt++)
                        mma_tf32(acc[mt][nt], af[mt], bf[nt]);
            }
            __syncthreads();
        }

        // --- epilogue ---
        #pragma unroll
        for (int mt = 0; mt < 4; mt++) {
            int rm0 = bm + wm * 64 + mt * 16 + g;
            #pragma unroll
            for (int nt = 0; nt < 4; nt++) {
                int col = bn + wn * 32 + nt * 8 + 2 * c;
                float2 bv = *(const float2*)(bias + col);
                if (rm0 < M) {
                    float2 o;
                    o.x = acc[mt][nt][0] + bv.x;
                    o.y = acc[mt][nt][1] + bv.y;
                    *(float2*)(C + (long)(rowbase + rm0) * N + col) = o;
                }
                if (rm0 + 8 < M) {
                    float2 o;
                    o.x = acc[mt][nt][2] + bv.x;
                    o.y = acc[mt][nt][3] + bv.y;
                    *(float2*)(C + (long)(rowbase + rm0 + 8) * N + col) = o;
                }
            }
        }
    }
}

// ---------------- GEGLU: O[m][j]=H[m][j]*gelu_exact(H[m][W+j]) ----------------
__global__ void geglu_kernel(const float* __restrict__ H, float* __restrict__ O,
                             int rows, int W) {
    long idx = (long)blockIdx.x * blockDim.x + threadIdx.x;  // over rows*W/4
    long total = (long)rows * (W >> 2);
    if (idx >= total) return;
    int wq = W >> 2;
    long m = idx / wq;
    int j = (int)(idx - m * wq) << 2;
    float4 a = *(const float4*)(H + m * 2 * W + j);
    float4 g = *(const float4*)(H + m * 2 * W + W + j);
    float4 o;
    o.x = a.x * (0.5f * g.x * (1.0f + erff(g.x * 0.70710678118654752f)));
    o.y = a.y * (0.5f * g.y * (1.0f + erff(g.y * 0.70710678118654752f)));
    o.z = a.z * (0.5f * g.z * (1.0f + erff(g.z * 0.70710678118654752f)));
    o.w = a.w * (0.5f * g.w * (1.0f + erff(g.w * 0.70710678118654752f)));
    *(float4*)(O + m * W + j) = o;
}

// ---------------- combine: out = ys + w0*yE[slot0] + w1*yE[slot1] ----------------
__global__ void combine_kernel(const float* __restrict__ ys,
                               const float* __restrict__ yE,
                               float* __restrict__ out) {
    int idx = blockIdx.x * blockDim.x + threadIdx.x;  // over Nt*Dm/4
    int n = idx >> 8;
    int d4 = (idx & 255) << 2;
    int s0 = g_slot[n * 2 + 0], s1 = g_slot[n * 2 + 1];
    float w0 = g_w[n * 2 + 0], w1 = g_w[n * 2 + 1];
    float4 a = *(const float4*)(ys + (long)n * Dm + d4);
    float4 b = *(const float4*)(yE + (long)s0 * Dm + d4);
    float4 cc = *(const float4*)(yE + (long)s1 * Dm + d4);
    float4 o;
    o.x = a.x + w0 * b.x + w1 * cc.x;
    o.y = a.y + w0 * b.y + w1 * cc.y;
    o.z = a.z + w0 * b.z + w1 * cc.z;
    o.w = a.w + w0 * b.w + w1 * cc.w;
    *(float4*)(out + (long)n * Dm + d4) = o;
}

// ---------------- launch ----------------
extern "C" void kernel_launch(void* const* d_in, const int* in_sizes, int n_in,
                              void* d_out, int out_size) {
    const float* x   = (const float*)d_in[0];
    const float* Ws1 = (const float*)d_in[1];
    const float* bs1 = (const float*)d_in[2];
    const float* Ws2 = (const float*)d_in[3];
    const float* bs2 = (const float*)d_in[4];
    const float* We1 = (const float*)d_in[5];
    const float* be1 = (const float*)d_in[6];
    const float* We2 = (const float*)d_in[7];
    const float* be2 = (const float*)d_in[8];
    const float* Wr  = (const float*)d_in[9];
    const float* br  = (const float*)d_in[10];
    float* out = (float*)d_out;

    float *pHs, *pAact, *pys, *pHr, *pAr, *pyE;
    int *pcnt, *poffs, *ptok;
    cudaGetSymbolAddress((void**)&pHs,   g_Hs);
    cudaGetSymbolAddress((void**)&pAact, g_Aact);
    cudaGetSymbolAddress((void**)&pys,   g_ys);
    cudaGetSymbolAddress((void**)&pHr,   g_Hr);
    cudaGetSymbolAddress((void**)&pAr,   g_Ar);
    cudaGetSymbolAddress((void**)&pyE,   g_yE);
    cudaGetSymbolAddress((void**)&pcnt,  g_cnt);
    cudaGetSymbolAddress((void**)&poffs, g_offs);
    cudaGetSymbolAddress((void**)&ptok,  g_tokrow);

    // 1) routing
    router_kernel<<<Nt, 128>>>(x, Wr, br);
    zero_cnt_kernel<<<1, 32>>>();
    count_kernel<<<(2 * Nt + 255) / 256, 256>>>();
    offs_kernel<<<1, 1>>>();
    fill_kernel<<<(2 * Nt + 255) / 256, 256>>>();

    // 2) shared expert
    tf32gemm<<<dim3(2 * HSdim / BN, Nt / BM, 1), 256>>>(
        x, Ws1, bs1, pHs, Nt, 2 * HSdim, Dm,
        nullptr, nullptr, nullptr, 0, 0);
    geglu_kernel<<<(unsigned)(((long)Nt * HSdim / 4 + 255) / 256), 256>>>(pHs, pAact, Nt, HSdim);
    tf32gemm<<<dim3(Dm / BN, Nt / BM, 1), 256>>>(
        pAact, Ws2, bs2, pys, Nt, Dm, HSdim,
        nullptr, nullptr, nullptr, 0, 0);

    // 3) routed experts (sparse dispatch: 4096 gathered rows total)
    tf32gemm<<<dim3(2 * HRdim / BN, 3, Ne), 256>>>(
        x, We1, be1, pHr, 0, 2 * HRdim, Dm,
        pcnt, poffs, ptok, (long)Dm * 2 * HRdim, 2 * HRdim);
    geglu_kernel<<<(unsigned)(((long)2 * Nt * HRdim / 4 + 255) / 256), 256>>>(pHr, pAr, 2 * Nt, HRdim);
    tf32gemm<<<dim3(Dm / BN, 4, Ne), 256>>>(
        pAr, We2, be2, pyE, 0, Dm, HRdim,
        pcnt, poffs, nullptr, (long)HRdim * Dm, Dm);

    // 4) combine
    combine_kernel<<<(Nt * Dm / 4) / 256, 256>>>(pys, pyE, out);
}